// round 8
// baseline (speedup 1.0000x reference)
#include <cuda_runtime.h>
#include <cuda_bf16.h>
#include <cstdint>

// Problem constants (fixed shapes for this dataset)
#define N_NODES 50000
#define N_BATCH 4
#define FEAT    32      // input feature dim, hidden1 dim, output dim
#define H2DIM   30      // hidden2 dim
#define ACC_W   32      // padded accumulator j-width (30 -> 32)

#define BN_MAX (N_BATCH * N_NODES)
#define GSTRIDE 144     // tile group stride in floats (bank-padded)

// Device scratch.
//   g_PaH/g_PbH : [node][k][b] bf16 (4 batches -> 8B per (node,k))
//   g_acc       : [b][node][j] f32 (j padded to 32) -- (j,j+1) pairs contiguous
__device__ unsigned short g_PaH[N_NODES * FEAT * N_BATCH];
__device__ unsigned short g_PbH[N_NODES * FEAT * N_BATCH];
__device__ float  g_acc[N_BATCH * N_NODES * ACC_W];
__device__ float  g_sum, g_sumsq;
__device__ int    g_is32;               // 1 if edge_index is int32, 0 if int64

// sigmoid via single MUFU.TANH: sig(x) = 0.5*tanh(x/2) + 0.5
__device__ __forceinline__ float sigf(float x) {
    float t;
    asm("tanh.approx.f32 %0, %1;" : "=f"(t) : "f"(x * 0.5f));
    return fmaf(t, 0.5f, 0.5f);
}

// exact bf16 -> f32 (bits<<16)
__device__ __forceinline__ float bf_lo(uint32_t u) { return __uint_as_float(u << 16); }
__device__ __forceinline__ float bf_hi(uint32_t u) { return __uint_as_float(u & 0xffff0000u); }

__device__ __forceinline__ uint32_t to_tf32(float v) {
    uint32_t r;
    asm("cvt.rna.tf32.f32 %0, %1;" : "=r"(r) : "f"(v));
    return r;
}

__device__ __forceinline__ void red2(float* p, float x, float y) {
    asm volatile("red.global.add.v2.f32 [%0], {%1, %2};"
                 :: "l"(p), "f"(x), "f"(y) : "memory");
}

// ---------------------------------------------------------------------------
// Fused init: zero accumulator + edge_attr stats + dtype detect
// ---------------------------------------------------------------------------
__global__ void k_init(int n_f4, const int* __restrict__ idx,
                       const float* __restrict__ ea, int E) {
    int i = blockIdx.x * blockDim.x + threadIdx.x;
    float4* p = reinterpret_cast<float4*>(g_acc);
    if (i < n_f4) p[i] = make_float4(0.f, 0.f, 0.f, 0.f);
    if (i == 0) { g_sum = 0.f; g_sumsq = 0.f; g_is32 = 0; }
    if (i < 2048) {
        if (idx[2 * i + 1] != 0) g_is32 = 1;   // benign race: only writes 1
    }

    float s = 0.f, ss = 0.f;
    for (int j = i; j < E; j += gridDim.x * blockDim.x) {
        float v = ea[j];
        s += v; ss += v * v;
    }
#pragma unroll
    for (int o = 16; o > 0; o >>= 1) {
        s  += __shfl_down_sync(0xffffffffu, s, o);
        ss += __shfl_down_sync(0xffffffffu, ss, o);
    }
    __shared__ float shs[8], shss[8];
    int w = threadIdx.x >> 5, l = threadIdx.x & 31;
    if (l == 0) { shs[w] = s; shss[w] = ss; }
    __syncthreads();
    if (threadIdx.x == 0) {
        float a = 0.f, b = 0.f;
        int nw = blockDim.x >> 5;
        for (int j = 0; j < nw; j++) { a += shs[j]; b += shss[j]; }
        if (a != 0.f || b != 0.f) {
            atomicAdd(&g_sum, a);
            atomicAdd(&g_sumsq, b);
        }
    }
}

// ---------------------------------------------------------------------------
// Per-(batch,node) projections: Pa = x@W1[0:32], Pb = x@W1[32:64] + b1.
// One warp per (b,node) row; stores bf16 into batch-interleaved layout.
// ---------------------------------------------------------------------------
__global__ void __launch_bounds__(256) k_proj(const float* __restrict__ x,
                                              const float* __restrict__ W1,
                                              const float* __restrict__ b1,
                                              int BN) {
    __shared__ float W1s[64 * 32];
    __shared__ float b1s[32];
    for (int i = threadIdx.x; i < 64 * 32; i += blockDim.x) W1s[i] = W1[i];
    if (threadIdx.x < 32) b1s[threadIdx.x] = b1[threadIdx.x];
    __syncthreads();

    int row = (blockIdx.x * blockDim.x + threadIdx.x) >> 5;
    int lane = threadIdx.x & 31;
    if (row >= BN) return;
    int b    = row / N_NODES;
    int node = row - b * N_NODES;

    float xv = x[row * 32 + lane];
    float pa = 0.f;
    float pb = b1s[lane];
#pragma unroll
    for (int k = 0; k < 32; k++) {
        float xk = __shfl_sync(0xffffffffu, xv, k);
        pa = fmaf(xk, W1s[k * 32 + lane], pa);
        pb = fmaf(xk, W1s[(32 + k) * 32 + lane], pb);
    }
    int o = (node * 32 + lane) * 4 + b;
    g_PaH[o] = __bfloat16_as_ushort(__float2bfloat16(pa));
    g_PbH[o] = __bfloat16_as_ushort(__float2bfloat16(pb));
}

// ---------------------------------------------------------------------------
// Edge kernel: warp processes a 4-edge tile.
// Phase A (per edge g): lane=k. 2x LDG.64 bf16 gather, h1 = sig(...), STS.128
//   into buf[g][k][b] (g-stride GSTRIDE floats, bank-padded).
// Phase B: m16n8k8 tf32 MMA: C[16x32] = h1[16x32] @ W2[32x32]; W2 in regs.
// Scatter: DIRECT from C fragments. Thread (gid,tid) holds rows gid & gid+8,
//   j = 8t+2tid, (j,j+1) -> contiguous float2 in acc[b][node][j] layout ->
//   red.global.add.v2.f32, no smem round-trip, no phase C.
// ---------------------------------------------------------------------------
__global__ void __launch_bounds__(256) k_edge(const int* __restrict__ idx,
                                              const float* __restrict__ ea,
                                              const float* __restrict__ W1,
                                              const float* __restrict__ W2,
                                              const float* __restrict__ b2,
                                              int E) {
    const int lane = threadIdx.x & 31;
    const int wid  = threadIdx.x >> 5;
    const int gid  = lane >> 2;       // mma group id 0..7
    const int tid  = lane & 3;        // mma thread-in-group
    const unsigned full = 0xffffffffu;

    // shared tile: h1, [warp][g][GSTRIDE]
    __shared__ __align__(16) float buf[8][4 * GSTRIDE];

    // ---- W2 tf32 fragments (B operand), loaded once ----
    uint32_t Bf[4][4][2];
#pragma unroll
    for (int s = 0; s < 4; s++) {
#pragma unroll
        for (int t = 0; t < 4; t++) {
            int j = 8 * t + gid;
            int k0 = 8 * s + tid;
            float w0 = (j < H2DIM) ? W2[k0 * H2DIM + j] : 0.f;
            float w1 = (j < H2DIM) ? W2[(k0 + 4) * H2DIM + j] : 0.f;
            Bf[s][t][0] = to_tf32(w0);
            Bf[s][t][1] = to_tf32(w1);
        }
    }

    // bias values for C init: j = 8t+2tid and +1
    float biasv[4][2];
#pragma unroll
    for (int t = 0; t < 4; t++) {
        int j = 8 * t + 2 * tid;
        biasv[t][0] = (j     < H2DIM) ? b2[j]     : 0.f;
        biasv[t][1] = (j + 1 < H2DIM) ? b2[j + 1] : 0.f;
    }

    // Per-lane constants for phase A (lane = k)
    float w1cv = W1[64 * 32 + lane];

    // finalize stats locally
    float s0  = g_sum, ss0 = g_sumsq;
    float mean   = s0 / (float)E;
    float invstd = rsqrtf((ss0 - s0 * s0 / (float)E) / (float)(E - 1));
    int   is32   = g_is32;

    int warp_global = (blockIdx.x * blockDim.x + threadIdx.x) >> 5;
    int base = warp_global * 32;
    if (base >= E) return;

    int e = base + lane;
    int src = 0, tgt = 0;
    float eav = 0.f;
    if (e < E) {
        if (is32) {
            src = idx[e];
            tgt = idx[E + e];
        } else {
            src = idx[2 * e];
            tgt = idx[2 * E + 2 * e];
        }
        eav = (ea[e] - mean) * invstd;
    }
    int cnt = min(32, E - base);

    const uint2* PaV = reinterpret_cast<const uint2*>(g_PaH);
    const uint2* PbV = reinterpret_cast<const uint2*>(g_PbH);

    uint32_t bufB = (uint32_t)__cvta_generic_to_shared(&buf[wid][0]);
    // A-fragment base: rows gid / gid+8 -> edges gid>>2 / +2, batch gid&3
    uint32_t aB  = bufB + (gid >> 2) * (GSTRIDE * 4) + tid * 16 + (gid & 3) * 4;

    // fragment (edge,batch) for scatter
    const int fe  = gid >> 2;       // fragment edge offset (rows gid)
    const int fb  = gid & 3;        // fragment batch
    float* accB = g_acc + fb * (N_NODES * ACC_W);

#pragma unroll 1
    for (int i = 0; i < cnt; i += 4) {
        // ---- Phase A: fill h1 for edges i..i+3 ----
#pragma unroll
        for (int g = 0; g < 4; g++) {
            int   eg = i + g;
            int   sg = __shfl_sync(full, src, eg);
            int   tg = __shfl_sync(full, tgt, eg);
            float ev = __shfl_sync(full, eav, eg);
            if (eg < cnt) {
                uint2 pa2 = PaV[sg * 32 + lane];
                uint2 pb2 = PbV[tg * 32 + lane];
                float c = ev * w1cv;
                float4 h;
                h.x = sigf(bf_lo(pa2.x) + bf_lo(pb2.x) + c);
                h.y = sigf(bf_hi(pa2.x) + bf_hi(pb2.x) + c);
                h.z = sigf(bf_lo(pa2.y) + bf_lo(pb2.y) + c);
                h.w = sigf(bf_hi(pa2.y) + bf_hi(pb2.y) + c);
                *reinterpret_cast<float4*>(&buf[wid][g * GSTRIDE + lane * 4]) = h;
            }
        }
        __syncwarp(full);

        // ---- Phase B: tf32 MMA, C[16x32] ----
        float c0[4], c1[4], c2[4], c3[4];
#pragma unroll
        for (int t = 0; t < 4; t++) {
            c0[t] = biasv[t][0]; c1[t] = biasv[t][1];
            c2[t] = biasv[t][0]; c3[t] = biasv[t][1];
        }
#pragma unroll
        for (int s = 0; s < 4; s++) {
            float fa0, fa1, fa2, fa3;
            uint32_t ad = aB + s * 128;           // k = 8s+tid -> 16B per k
            asm("ld.shared.b32 %0, [%1];"       : "=f"(fa0) : "r"(ad));
            asm("ld.shared.b32 %0, [%1+1152];"  : "=f"(fa1) : "r"(ad));  // g+2
            asm("ld.shared.b32 %0, [%1+64];"    : "=f"(fa2) : "r"(ad));  // k+4
            asm("ld.shared.b32 %0, [%1+1216];"  : "=f"(fa3) : "r"(ad));
            uint32_t a0 = to_tf32(fa0), a1 = to_tf32(fa1);
            uint32_t a2 = to_tf32(fa2), a3 = to_tf32(fa3);
#pragma unroll
            for (int t = 0; t < 4; t++) {
                asm("mma.sync.aligned.m16n8k8.row.col.f32.tf32.tf32.f32 "
                    "{%0,%1,%2,%3}, {%4,%5,%6,%7}, {%8,%9}, {%0,%1,%2,%3};"
                    : "+f"(c0[t]), "+f"(c1[t]), "+f"(c2[t]), "+f"(c3[t])
                    : "r"(a0), "r"(a1), "r"(a2), "r"(a3),
                      "r"(Bf[s][t][0]), "r"(Bf[s][t][1]));
            }
        }

        // ---- direct fragment scatter (rows gid & gid+8) ----
        int e0 = i + fe;            // rows gid
        int e1 = e0 + 2;            // rows gid+8
        bool a0v = e0 < cnt;
        bool a1v = e1 < cnt;
        int  t0 = __shfl_sync(full, tgt, e0 & 31);
        int  s0w = __shfl_sync(full, src, e0 & 31);
        int  t1 = __shfl_sync(full, tgt, e1 & 31);
        int  s1w = __shfl_sync(full, src, e1 & 31);

        float* rowT0 = accB + t0 * ACC_W;
        float* rowS0 = accB + s0w * ACC_W;
        float* rowT1 = accB + t1 * ACC_W;
        float* rowS1 = accB + s1w * ACC_W;

#pragma unroll
        for (int t = 0; t < 4; t++) {
            int j = 8 * t + 2 * tid;
            if (j < H2DIM) {        // skips only t=3,tid=3 (j=30)
                if (a0v) {
                    float v0 = sigf(c0[t]), v1 = sigf(c1[t]);
                    red2(rowT0 + j,  v0,  v1);
                    red2(rowS0 + j, -v0, -v1);
                }
                if (a1v) {
                    float v2 = sigf(c2[t]), v3 = sigf(c3[t]);
                    red2(rowT1 + j,  v2,  v3);
                    red2(rowS1 + j, -v2, -v3);
                }
            }
        }
        __syncwarp(full);   // A-frag reads done before next tile's STS
    }
}

// ---------------------------------------------------------------------------
// Output: out[row][:] = sigmoid(acc[row][:30] @ W3 + b3), row = b*N+node.
// One warp per row; lane = output column; acc row broadcast via shfl.
// ---------------------------------------------------------------------------
__global__ void __launch_bounds__(256) k_out(const float* __restrict__ W3,
                                             const float* __restrict__ b3,
                                             float* __restrict__ out,
                                             int BN) {
    __shared__ float W3s[30 * 32];
    __shared__ float b3s[32];
    for (int i = threadIdx.x; i < 30 * 32; i += blockDim.x) W3s[i] = W3[i];
    if (threadIdx.x < 32) b3s[threadIdx.x] = b3[threadIdx.x];
    __syncthreads();

    int row = (blockIdx.x * blockDim.x + threadIdx.x) >> 5;
    int lane = threadIdx.x & 31;
    if (row >= BN) return;
    const unsigned full = 0xffffffffu;

    float av = g_acc[row * ACC_W + lane];   // lanes 30/31 read padding (unused)
    float o = b3s[lane];
#pragma unroll
    for (int k = 0; k < 30; k++) {
        float ak = __shfl_sync(full, av, k);
        o = fmaf(ak, W3s[k * 32 + lane], o);
    }
    out[row * 32 + lane] = sigf(o);
}

// ---------------------------------------------------------------------------
extern "C" void kernel_launch(void* const* d_in, const int* in_sizes, int n_in,
                              void* d_out, int out_size) {
    const float* x  = (const float*)d_in[0];
    const int*   ix = (const int*)  d_in[1];
    const float* ea = (const float*)d_in[2];
    const float* W1 = (const float*)d_in[3];
    const float* b1 = (const float*)d_in[4];
    const float* W2 = (const float*)d_in[5];
    const float* b2 = (const float*)d_in[6];
    const float* W3 = (const float*)d_in[7];
    const float* b3 = (const float*)d_in[8];

    int E  = in_sizes[2];            // edge_attr has E elements
    int BN = in_sizes[0] / FEAT;     // B * N rows

    int n_f4 = N_BATCH * N_NODES * ACC_W / 4;
    k_init<<<(n_f4 + 255) / 256, 256>>>(n_f4, ix, ea, E);
    k_proj<<<(BN + 7) / 8, 256>>>(x, W1, b1, BN);

    int warps = (E + 31) / 32;
    int blocks = (warps + 7) / 8;    // 8 warps (256 threads) per block
    k_edge<<<blocks, 256>>>(ix, ea, W1, W2, b2, E);

    k_out<<<(BN + 7) / 8, 256>>>(W3, b3, (float*)d_out, BN);
}